// round 4
// baseline (speedup 1.0000x reference)
#include <cuda_runtime.h>

#define NN 100000
#define EE 600000
#define D 128

// ---- static device scratch (allocation-free rule: __device__ globals,
// referenced ONLY from device code — no cudaGetSymbolAddress) ----
__device__ float g_h[NN * D];      // post-GEMM features (51.2 MB)
__device__ float g_x[NN * D];      // post-aggregation features (51.2 MB)
__device__ float g_dinv[NN];
__device__ float g_degw[NN];
__device__ int   g_cnt[NN];
__device__ int   g_cur[NN];
__device__ int   g_off[NN + 1];
__device__ int   g_csrc[EE];       // CSR: source node per bucketed edge
__device__ float g_cnorm[EE];      // CSR: norm coefficient per bucketed edge

// ---------------------------------------------------------------- zero
__global__ void k_zero(int n) {
    int i = blockIdx.x * blockDim.x + threadIdx.x;
    if (i < n) { g_degw[i] = 0.f; g_cnt[i] = 0; g_cur[i] = 0; }
}

// ------------------------------------------------- degree / count pass
// NOTE: edge_index is int32 (JAX x64 disabled downgrades jnp.int64).
__global__ void k_count(const int* __restrict__ ei,
                        const float* __restrict__ ew, int e) {
    int i = blockIdx.x * blockDim.x + threadIdx.x;
    if (i < e) {
        int dst = ei[e + i];
        atomicAdd(&g_cnt[dst], 1);
        atomicAdd(&g_degw[dst], ew[i]);
    }
}

__global__ void k_dinv(int n) {
    int i = blockIdx.x * blockDim.x + threadIdx.x;
    if (i < n) g_dinv[i] = rsqrtf(g_degw[i] + 1.0f);
}

// --------------------------------- single-block exclusive scan of g_cnt
__global__ void k_scan(int n) {
    __shared__ int s[1024];
    int tid = threadIdx.x;
    int chunk = (n + 1023) >> 10;
    int beg = tid * chunk;
    int end = min(beg + chunk, n);
    int sum = 0;
    for (int i = beg; i < end; i++) sum += g_cnt[i];
    s[tid] = sum;
    __syncthreads();
    for (int off = 1; off < 1024; off <<= 1) {
        int t = (tid >= off) ? s[tid - off] : 0;
        __syncthreads();
        s[tid] += t;
        __syncthreads();
    }
    int run = s[tid] - sum;   // exclusive prefix
    for (int i = beg; i < end; i++) { g_off[i] = run; run += g_cnt[i]; }
    if (tid == 0) g_off[n] = s[1023];
}

// --------------------------------------- bucket edges into CSR + norms
__global__ void k_bucket(const int* __restrict__ ei,
                         const float* __restrict__ ew, int e) {
    int i = blockIdx.x * blockDim.x + threadIdx.x;
    if (i < e) {
        int src = ei[i];
        int dst = ei[e + i];
        int pos = g_off[dst] + atomicAdd(&g_cur[dst], 1);
        g_csrc[pos] = src;
        g_cnorm[pos] = g_dinv[src] * ew[i] * g_dinv[dst];
    }
}

// ---------------------------------------------------------------- GEMM
// g_h[n,128] = (SRC_GX? relu(g_x) : X)[n,128] @ W[128,128]
// 256 threads, 64 rows/block. X tile pair-interleaved in 32 KB static smem
// (two consecutive rows form a f32x2 operand -> packed FMA). W stays in
// L1 (64 KB, block-invariant, coalesced __ldg).
__device__ __forceinline__ void fma2(unsigned long long& d,
                                     unsigned long long a,
                                     unsigned long long b) {
    asm("fma.rn.f32x2 %0, %1, %2, %3;" : "=l"(d) : "l"(a), "l"(b), "l"(d));
}

template <bool SRC_GX>
__global__ void __launch_bounds__(256) k_gemm(const float* __restrict__ Xarg,
                                              const float* __restrict__ W,
                                              int nrows) {
    __shared__ float Xs[64 * D];   // 32 KB, pair-interleaved
    int tid = threadIdx.x;

    int row0 = blockIdx.x * 64;
    int nr = min(64, nrows - row0);
    const float* Xsrc = SRC_GX ? (const float*)g_x : Xarg;
    const float4* X4 = (const float4*)(Xsrc + (size_t)row0 * D);
    for (int i = tid; i < nr * (D / 4); i += 256) {
        float4 v = X4[i];
        if (SRC_GX) {   // layer-2 path fuses the relu
            v.x = fmaxf(v.x, 0.f); v.y = fmaxf(v.y, 0.f);
            v.z = fmaxf(v.z, 0.f); v.w = fmaxf(v.w, 0.f);
        }
        int row = i >> 5;
        int kb = (i & 31) << 2;
        int base = ((row >> 1) << 8) + (row & 1);  // (row/2)*256 + parity
        Xs[base + ((kb + 0) << 1)] = v.x;
        Xs[base + ((kb + 1) << 1)] = v.y;
        Xs[base + ((kb + 2) << 1)] = v.z;
        Xs[base + ((kb + 3) << 1)] = v.w;
    }
    __syncthreads();

    int warp = tid >> 5, lane = tid & 31;
    unsigned long long acc[4][4];
#pragma unroll
    for (int a = 0; a < 4; a++)
#pragma unroll
        for (int b = 0; b < 4; b++) acc[a][b] = 0ull;

    const unsigned long long* Xp = (const unsigned long long*)Xs;
    const float4* W4 = (const float4*)W;

#pragma unroll 4
    for (int k = 0; k < D; k++) {
        float4 wv = __ldg(&W4[k * 32 + lane]);  // cols 4*lane..4*lane+3, L1-hot
        unsigned long long w0, w1, w2, w3;
        asm("mov.b64 %0, {%1, %1};" : "=l"(w0) : "f"(wv.x));
        asm("mov.b64 %0, {%1, %1};" : "=l"(w1) : "f"(wv.y));
        asm("mov.b64 %0, {%1, %1};" : "=l"(w2) : "f"(wv.z));
        asm("mov.b64 %0, {%1, %1};" : "=l"(w3) : "f"(wv.w));
#pragma unroll
        for (int rp = 0; rp < 4; rp++) {
            unsigned long long xp = Xp[(warp * 4 + rp) * D + k];  // bcast LDS
            fma2(acc[rp][0], xp, w0);
            fma2(acc[rp][1], xp, w1);
            fma2(acc[rp][2], xp, w2);
            fma2(acc[rp][3], xp, w3);
        }
    }

    float4* H4 = (float4*)g_h;
#pragma unroll
    for (int rp = 0; rp < 4; rp++) {
        int rA = row0 + warp * 8 + rp * 2;
        int rB = rA + 1;
        float lo[4], hi[4];
#pragma unroll
        for (int c = 0; c < 4; c++)
            asm("mov.b64 {%0, %1}, %2;" : "=f"(lo[c]), "=f"(hi[c]) : "l"(acc[rp][c]));
        if (rA < nrows) {
            float4 o; o.x = lo[0]; o.y = lo[1]; o.z = lo[2]; o.w = lo[3];
            H4[rA * 32 + lane] = o;
        }
        if (rB < nrows) {
            float4 o; o.x = hi[0]; o.y = hi[1]; o.z = hi[2]; o.w = hi[3];
            H4[rB * 32 + lane] = o;
        }
    }
}

// ------------------------------------------------ per-node aggregation
// g_x[i] = b + dinv[i]^2 * g_h[i] + sum_{edges into i} norm * g_h[src]
// warp per node; lane handles 4 features (float4). No fp atomics.
__global__ void __launch_bounds__(256) k_agg(const float* __restrict__ b, int n) {
    int warp = threadIdx.x >> 5, lane = threadIdx.x & 31;
    int i = blockIdx.x * 8 + warp;
    if (i >= n) return;
    float di = g_dinv[i];
    float ds = di * di;
    const float4* h4 = (const float4*)g_h;
    float4 hv = h4[i * 32 + lane];
    float4 bv = ((const float4*)b)[lane];
    float4 acc;
    acc.x = fmaf(hv.x, ds, bv.x);
    acc.y = fmaf(hv.y, ds, bv.y);
    acc.z = fmaf(hv.z, ds, bv.z);
    acc.w = fmaf(hv.w, ds, bv.w);
    int p0 = g_off[i], p1 = g_off[i + 1];
    for (int p = p0; p < p1; p++) {
        int s = g_csrc[p];          // broadcast within warp
        float nm = g_cnorm[p];
        float4 v = h4[s * 32 + lane];
        acc.x = fmaf(v.x, nm, acc.x);
        acc.y = fmaf(v.y, nm, acc.y);
        acc.z = fmaf(v.z, nm, acc.z);
        acc.w = fmaf(v.w, nm, acc.w);
    }
    ((float4*)g_x)[i * 32 + lane] = acc;
}

// --------------------------------------------- final head: relu(x) @ Wl + bl
__global__ void __launch_bounds__(256) k_final(const float* __restrict__ Wl,
                                               const float* __restrict__ bl,
                                               float* __restrict__ out, int n) {
    int warp = threadIdx.x >> 5, lane = threadIdx.x & 31;
    int i = blockIdx.x * 8 + warp;
    if (i >= n) return;
    float4 xv = ((const float4*)g_x)[i * 32 + lane];
    float4 wv = ((const float4*)Wl)[lane];
    float a = fmaxf(xv.x, 0.f) * wv.x + fmaxf(xv.y, 0.f) * wv.y +
              fmaxf(xv.z, 0.f) * wv.z + fmaxf(xv.w, 0.f) * wv.w;
#pragma unroll
    for (int o = 16; o; o >>= 1) a += __shfl_xor_sync(0xffffffffu, a, o);
    if (lane == 0) out[i] = a + bl[0];
}

// ---------------------------------------------------------------- launch
extern "C" void kernel_launch(void* const* d_in, const int* in_sizes, int n_in,
                              void* d_out, int out_size) {
    const float* wx = (const float*)d_in[0];
    const int*   ei = (const int*)d_in[1];     // int32! (JAX x64 disabled)
    const float* ew = (const float*)d_in[2];
    const float* W1 = (const float*)d_in[3];
    const float* b1 = (const float*)d_in[4];
    const float* W2 = (const float*)d_in[5];
    const float* b2 = (const float*)d_in[6];
    const float* Wl = (const float*)d_in[7];
    const float* bl = (const float*)d_in[8];
    float* out = (float*)d_out;

    int n = in_sizes[0] / D;   // 100000
    int e = in_sizes[2];       // 600000 (edge_weight count — dtype-proof)

    int nb = (n + 255) / 256;
    int eb = (e + 255) / 256;

    // graph preprocessing (rebuilt every launch; edges are an input)
    k_zero  <<<nb, 256>>>(n);
    k_count <<<eb, 256>>>(ei, ew, e);
    k_dinv  <<<nb, 256>>>(n);
    k_scan  <<<1, 1024>>>(n);
    k_bucket<<<eb, 256>>>(ei, ew, e);

    // layer 1: h = wx @ W1  -> g_h ; then aggregate -> g_x
    k_gemm<false><<<(n + 63) / 64, 256>>>(wx, W1, n);
    k_agg        <<<(n + 7) / 8, 256>>>(b1, n);
    // layer 2: h = relu(g_x) @ W2 -> g_h ; aggregate -> g_x
    k_gemm<true> <<<(n + 63) / 64, 256>>>(nullptr, W2, n);
    k_agg        <<<(n + 7) / 8, 256>>>(b2, n);
    // head (relu fused)
    k_final      <<<(n + 7) / 8, 256>>>(Wl, bl, out, n);
}

// round 5
// speedup vs baseline: 1.2671x; 1.2671x over previous
#include <cuda_runtime.h>

#define NN 100000
#define EE 600000
#define D 128

// ---- static device scratch (allocation-free rule: __device__ globals) ----
__device__ float g_h[NN * D];      // post-GEMM features (51.2 MB)
__device__ float g_x[NN * D];      // post-aggregation features (51.2 MB)
__device__ float g_dinv[NN];
__device__ float g_degw[NN];
__device__ int   g_cnt[NN];
__device__ int   g_cur[NN];
__device__ int   g_off[NN];        // slot base per node (NOT monotonic)
__device__ int   g_total;          // CSR slot allocator
__device__ int   g_csrc[EE];       // CSR: source node per bucketed edge
__device__ float g_cnorm[EE];      // CSR: norm coefficient per bucketed edge

// ---------------------------------------------------------------- zero
__global__ void k_zero(int n) {
    int i = blockIdx.x * blockDim.x + threadIdx.x;
    if (i < n) { g_degw[i] = 0.f; g_cnt[i] = 0; g_cur[i] = 0; }
    if (i == 0) g_total = 0;
}

// ------------------------------------------------- degree / count pass
// edge_index is int32 (JAX x64 disabled downgrades jnp.int64).
__global__ void k_count(const int* __restrict__ ei,
                        const float* __restrict__ ew, int e) {
    int i = blockIdx.x * blockDim.x + threadIdx.x;
    if (i < e) {
        int dst = ei[e + i];
        atomicAdd(&g_cnt[dst], 1);
        atomicAdd(&g_degw[dst], ew[i]);
    }
}

// -------------------- per-node: dinv + CSR slot reservation (no scan)
// Offsets need only be disjoint, not ordered: warp-scan counts, one
// atomicAdd per warp on the global allocator, broadcast base + prefix.
__global__ void k_node(int n) {
    int i = blockIdx.x * blockDim.x + threadIdx.x;
    int lane = threadIdx.x & 31;
    if (i < n) g_dinv[i] = rsqrtf(g_degw[i] + 1.0f);
    int c = (i < n) ? g_cnt[i] : 0;
    int pfx = c;
#pragma unroll
    for (int o = 1; o < 32; o <<= 1) {
        int t = __shfl_up_sync(0xffffffffu, pfx, o);
        if (lane >= o) pfx += t;
    }
    int wsum = __shfl_sync(0xffffffffu, pfx, 31);
    int base = 0;
    if (lane == 31) base = atomicAdd(&g_total, wsum);
    base = __shfl_sync(0xffffffffu, base, 31);
    if (i < n) g_off[i] = base + pfx - c;
}

// --------------------------------------- bucket edges into CSR + norms
__global__ void k_bucket(const int* __restrict__ ei,
                         const float* __restrict__ ew, int e) {
    int i = blockIdx.x * blockDim.x + threadIdx.x;
    if (i < e) {
        int src = ei[i];
        int dst = ei[e + i];
        int pos = g_off[dst] + atomicAdd(&g_cur[dst], 1);
        g_csrc[pos] = src;
        g_cnorm[pos] = g_dinv[src] * ew[i] * g_dinv[dst];
    }
}

// ---------------------------------------------------------------- GEMM
// g_h[n,128] = (SRC_GX? relu(g_x) : X)[n,128] @ W[128,128]
// 256 threads, 64 rows/block. X tile pair-interleaved in 32 KB static smem
// (two consecutive rows form a f32x2 operand -> packed FMA). W stays in
// L1 (64 KB, block-invariant, coalesced __ldg).
__device__ __forceinline__ void fma2(unsigned long long& d,
                                     unsigned long long a,
                                     unsigned long long b) {
    asm("fma.rn.f32x2 %0, %1, %2, %3;" : "=l"(d) : "l"(a), "l"(b), "l"(d));
}

template <bool SRC_GX>
__global__ void __launch_bounds__(256) k_gemm(const float* __restrict__ Xarg,
                                              const float* __restrict__ W,
                                              int nrows) {
    __shared__ float Xs[64 * D];   // 32 KB, pair-interleaved
    int tid = threadIdx.x;

    int row0 = blockIdx.x * 64;
    int nr = min(64, nrows - row0);
    const float* Xsrc = SRC_GX ? (const float*)g_x : Xarg;
    const float4* X4 = (const float4*)(Xsrc + (size_t)row0 * D);
    for (int i = tid; i < nr * (D / 4); i += 256) {
        float4 v = X4[i];
        if (SRC_GX) {   // layer-2 path fuses the relu
            v.x = fmaxf(v.x, 0.f); v.y = fmaxf(v.y, 0.f);
            v.z = fmaxf(v.z, 0.f); v.w = fmaxf(v.w, 0.f);
        }
        int row = i >> 5;
        int kb = (i & 31) << 2;
        int base = ((row >> 1) << 8) + (row & 1);  // (row/2)*256 + parity
        Xs[base + ((kb + 0) << 1)] = v.x;
        Xs[base + ((kb + 1) << 1)] = v.y;
        Xs[base + ((kb + 2) << 1)] = v.z;
        Xs[base + ((kb + 3) << 1)] = v.w;
    }
    __syncthreads();

    int warp = tid >> 5, lane = tid & 31;
    unsigned long long acc[4][4];
#pragma unroll
    for (int a = 0; a < 4; a++)
#pragma unroll
        for (int b = 0; b < 4; b++) acc[a][b] = 0ull;

    const unsigned long long* Xp = (const unsigned long long*)Xs;
    const float4* W4 = (const float4*)W;

#pragma unroll 4
    for (int k = 0; k < D; k++) {
        float4 wv = __ldg(&W4[k * 32 + lane]);  // cols 4*lane..4*lane+3, L1-hot
        unsigned long long w0, w1, w2, w3;
        asm("mov.b64 %0, {%1, %1};" : "=l"(w0) : "f"(wv.x));
        asm("mov.b64 %0, {%1, %1};" : "=l"(w1) : "f"(wv.y));
        asm("mov.b64 %0, {%1, %1};" : "=l"(w2) : "f"(wv.z));
        asm("mov.b64 %0, {%1, %1};" : "=l"(w3) : "f"(wv.w));
#pragma unroll
        for (int rp = 0; rp < 4; rp++) {
            unsigned long long xp = Xp[(warp * 4 + rp) * D + k];  // bcast LDS
            fma2(acc[rp][0], xp, w0);
            fma2(acc[rp][1], xp, w1);
            fma2(acc[rp][2], xp, w2);
            fma2(acc[rp][3], xp, w3);
        }
    }

    float4* H4 = (float4*)g_h;
#pragma unroll
    for (int rp = 0; rp < 4; rp++) {
        int rA = row0 + warp * 8 + rp * 2;
        int rB = rA + 1;
        float lo[4], hi[4];
#pragma unroll
        for (int c = 0; c < 4; c++)
            asm("mov.b64 {%0, %1}, %2;" : "=f"(lo[c]), "=f"(hi[c]) : "l"(acc[rp][c]));
        if (rA < nrows) {
            float4 o; o.x = lo[0]; o.y = lo[1]; o.z = lo[2]; o.w = lo[3];
            H4[rA * 32 + lane] = o;
        }
        if (rB < nrows) {
            float4 o; o.x = hi[0]; o.y = hi[1]; o.z = hi[2]; o.w = hi[3];
            H4[rB * 32 + lane] = o;
        }
    }
}

// ------------------------------------------------ per-node aggregation
// g_x[i] = b + dinv[i]^2 * g_h[i] + sum_{edges into i} norm * g_h[src]
// warp per node; lane handles 4 features (float4). No fp atomics.
__global__ void __launch_bounds__(256) k_agg(const float* __restrict__ b, int n) {
    int warp = threadIdx.x >> 5, lane = threadIdx.x & 31;
    int i = blockIdx.x * 8 + warp;
    if (i >= n) return;
    float di = g_dinv[i];
    float ds = di * di;
    const float4* h4 = (const float4*)g_h;
    float4 hv = h4[i * 32 + lane];
    float4 bv = ((const float4*)b)[lane];
    float4 acc;
    acc.x = fmaf(hv.x, ds, bv.x);
    acc.y = fmaf(hv.y, ds, bv.y);
    acc.z = fmaf(hv.z, ds, bv.z);
    acc.w = fmaf(hv.w, ds, bv.w);
    int p0 = g_off[i], p1 = p0 + g_cnt[i];   // offsets are disjoint, not sorted
    for (int p = p0; p < p1; p++) {
        int s = g_csrc[p];          // broadcast within warp
        float nm = g_cnorm[p];
        float4 v = h4[s * 32 + lane];
        acc.x = fmaf(v.x, nm, acc.x);
        acc.y = fmaf(v.y, nm, acc.y);
        acc.z = fmaf(v.z, nm, acc.z);
        acc.w = fmaf(v.w, nm, acc.w);
    }
    ((float4*)g_x)[i * 32 + lane] = acc;
}

// --------------------------------------------- final head: relu(x) @ Wl + bl
__global__ void __launch_bounds__(256) k_final(const float* __restrict__ Wl,
                                               const float* __restrict__ bl,
                                               float* __restrict__ out, int n) {
    int warp = threadIdx.x >> 5, lane = threadIdx.x & 31;
    int i = blockIdx.x * 8 + warp;
    if (i >= n) return;
    float4 xv = ((const float4*)g_x)[i * 32 + lane];
    float4 wv = ((const float4*)Wl)[lane];
    float a = fmaxf(xv.x, 0.f) * wv.x + fmaxf(xv.y, 0.f) * wv.y +
              fmaxf(xv.z, 0.f) * wv.z + fmaxf(xv.w, 0.f) * wv.w;
#pragma unroll
    for (int o = 16; o; o >>= 1) a += __shfl_xor_sync(0xffffffffu, a, o);
    if (lane == 0) out[i] = a + bl[0];
}

// ---------------------------------------------------------------- launch
extern "C" void kernel_launch(void* const* d_in, const int* in_sizes, int n_in,
                              void* d_out, int out_size) {
    const float* wx = (const float*)d_in[0];
    const int*   ei = (const int*)d_in[1];     // int32! (JAX x64 disabled)
    const float* ew = (const float*)d_in[2];
    const float* W1 = (const float*)d_in[3];
    const float* b1 = (const float*)d_in[4];
    const float* W2 = (const float*)d_in[5];
    const float* b2 = (const float*)d_in[6];
    const float* Wl = (const float*)d_in[7];
    const float* bl = (const float*)d_in[8];
    float* out = (float*)d_out;

    int n = in_sizes[0] / D;   // 100000
    int e = in_sizes[2];       // 600000 (edge_weight count — dtype-proof)

    int nb = (n + 255) / 256;
    int eb = (e + 255) / 256;

    // graph preprocessing (rebuilt every launch; edges are an input)
    k_zero  <<<nb, 256>>>(n);
    k_count <<<eb, 256>>>(ei, ew, e);
    k_node  <<<nb, 256>>>(n);              // dinv + slot reservation (no scan)
    k_bucket<<<eb, 256>>>(ei, ew, e);

    // layer 1: h = wx @ W1  -> g_h ; then aggregate -> g_x
    k_gemm<false><<<(n + 63) / 64, 256>>>(wx, W1, n);
    k_agg        <<<(n + 7) / 8, 256>>>(b1, n);
    // layer 2: h = relu(g_x) @ W2 -> g_h ; aggregate -> g_x
    k_gemm<true> <<<(n + 63) / 64, 256>>>(nullptr, W2, n);
    k_agg        <<<(n + 7) / 8, 256>>>(b2, n);
    // head (relu fused)
    k_final      <<<(n + 7) / 8, 256>>>(Wl, bl, out, n);
}

// round 7
// speedup vs baseline: 1.9438x; 1.5341x over previous
#include <cuda_runtime.h>
#include <cuda_bf16.h>
#include <cstdint>

#define NN 100000
#define EE 600000
#define D 128
#define TM 128           // rows per GEMM block
#define ST 40            // smem row stride in bf16 (32 data + 8 pad) -> conflict-free frags

// ---- static device scratch ----
__device__ float g_h[NN * D];
__device__ float g_x[NN * D];
__device__ float g_dinv[NN];
__device__ float g_degw[NN];
__device__ int   g_cnt[NN];
__device__ int   g_cur[NN];
__device__ int   g_off[NN];
__device__ int   g_total;
__device__ int   g_csrc[EE];
__device__ float g_cnorm[EE];
// pre-split W^T images, row-major [n][k] bf16: [matrix][hi/lo]
__device__ __align__(16) __nv_bfloat16 g_wimg[2][2][D * D];

// =========================== preprocessing ==================================
__global__ void k_zero(int n) {
    int i = blockIdx.x * blockDim.x + threadIdx.x;
    if (i < n) { g_degw[i] = 0.f; g_cnt[i] = 0; g_cur[i] = 0; }
    if (i == 0) g_total = 0;
}

// edge_index is int32 (JAX x64 disabled downgrades jnp.int64).
__global__ void k_count(const int* __restrict__ ei,
                        const float* __restrict__ ew, int e) {
    int i = blockIdx.x * blockDim.x + threadIdx.x;
    if (i < e) {
        int dst = ei[e + i];
        atomicAdd(&g_cnt[dst], 1);
        atomicAdd(&g_degw[dst], ew[i]);
    }
}

// per-node: dinv + CSR slot reservation (warp-scan + one atomic per warp)
__global__ void k_node(int n) {
    int i = blockIdx.x * blockDim.x + threadIdx.x;
    int lane = threadIdx.x & 31;
    if (i < n) g_dinv[i] = rsqrtf(g_degw[i] + 1.0f);
    int c = (i < n) ? g_cnt[i] : 0;
    int pfx = c;
#pragma unroll
    for (int o = 1; o < 32; o <<= 1) {
        int t = __shfl_up_sync(0xffffffffu, pfx, o);
        if (lane >= o) pfx += t;
    }
    int wsum = __shfl_sync(0xffffffffu, pfx, 31);
    int base = 0;
    if (lane == 31) base = atomicAdd(&g_total, wsum);
    base = __shfl_sync(0xffffffffu, base, 31);
    if (i < n) g_off[i] = base + pfx - c;
}

__global__ void k_bucket(const int* __restrict__ ei,
                         const float* __restrict__ ew, int e) {
    int i = blockIdx.x * blockDim.x + threadIdx.x;
    if (i < e) {
        int src = ei[i];
        int dst = ei[e + i];
        int pos = g_off[dst] + atomicAdd(&g_cur[dst], 1);
        g_csrc[pos] = src;
        g_cnorm[pos] = g_dinv[src] * ew[i] * g_dinv[dst];
    }
}

// split W1/W2 into bf16 hi/lo W^T images, row-major [n][k]
__global__ void k_wsplit(const float* __restrict__ W1,
                         const float* __restrict__ W2) {
    int i = blockIdx.x * blockDim.x + threadIdx.x;  // 0..32767
    int m = i >> 14;
    int idx = i & 16383;
    int k = idx >> 7, nn_ = idx & 127;
    const float* W = m ? W2 : W1;
    float w = W[k * D + nn_];
    __nv_bfloat16 h = __float2bfloat16(w);
    __nv_bfloat16 l = __float2bfloat16(w - __bfloat162float(h));
    g_wimg[m][0][nn_ * D + k] = h;   // W^T[n][k]
    g_wimg[m][1][nn_ * D + k] = l;
}

// ===================== tensor-core GEMM via mma.sync (bf16 3-MMA split) =====
// g_h[128 x 128 tile] = X @ W  with D = A @ B^T fragments:
//   A = X hi/lo (m16n8k16 A-frag, direct LDS), B = W^T hi/lo.
#define MMA_BF16(d, a, b) \
    asm volatile("mma.sync.aligned.m16n8k16.row.col.f32.bf16.bf16.f32 " \
        "{%0,%1,%2,%3}, {%4,%5,%6,%7}, {%8,%9}, {%0,%1,%2,%3};" \
        : "+f"((d)[0]), "+f"((d)[1]), "+f"((d)[2]), "+f"((d)[3]) \
        : "r"((a)[0]), "r"((a)[1]), "r"((a)[2]), "r"((a)[3]), \
          "r"((b)[0]), "r"((b)[1]))

template <bool SRC_GX>
__global__ void __launch_bounds__(256) k_gemm_mma(const float* __restrict__ Xarg,
                                                  int bsel, int nrows) {
    __shared__ __nv_bfloat16 sXh[TM * ST];   // 10 KB each
    __shared__ __nv_bfloat16 sXl[TM * ST];
    __shared__ __nv_bfloat16 sWh[D * ST];
    __shared__ __nv_bfloat16 sWl[D * ST];

    int tid = threadIdx.x;
    int wid = tid >> 5, lane = tid & 31;
    int g = lane >> 2, t = lane & 3;      // frag group / thread-in-group
    int mr0 = (wid & 3) * 32;             // warp's 32 rows within the tile
    int nb  = (wid >> 2) * 64;            // warp's 64-col half

    int row0 = blockIdx.x * TM;
    const float* Xsrc = SRC_GX ? (const float*)g_x : Xarg;
    const __nv_bfloat16* Wh = g_wimg[bsel][0];
    const __nv_bfloat16* Wl = g_wimg[bsel][1];

    float acc[2][8][4];
#pragma unroll
    for (int a = 0; a < 2; a++)
#pragma unroll
        for (int b = 0; b < 8; b++)
#pragma unroll
            for (int c = 0; c < 4; c++) acc[a][b][c] = 0.f;

    int srow = tid >> 1;                  // staging: thread -> row, half
    int shalf = (tid & 1) * 16;

    for (int k0 = 0; k0 < D; k0 += 32) {
        __syncthreads();
        // ---- stage X chunk (fp32 -> bf16 hi/lo) ----
        {
            int grow = row0 + srow;
            if (grow < nrows) {
                const float4* xr = (const float4*)(Xsrc + (size_t)grow * D + k0 + shalf);
#pragma unroll
                for (int j = 0; j < 4; j++) {
                    float4 v = xr[j];
                    if (SRC_GX) {
                        v.x = fmaxf(v.x, 0.f); v.y = fmaxf(v.y, 0.f);
                        v.z = fmaxf(v.z, 0.f); v.w = fmaxf(v.w, 0.f);
                    }
                    __nv_bfloat162 h0 = __float22bfloat162_rn(make_float2(v.x, v.y));
                    __nv_bfloat162 h1 = __float22bfloat162_rn(make_float2(v.z, v.w));
                    float2 f0 = __bfloat1622float2(h0);
                    float2 f1 = __bfloat1622float2(h1);
                    __nv_bfloat162 l0 = __float22bfloat162_rn(make_float2(v.x - f0.x, v.y - f0.y));
                    __nv_bfloat162 l1 = __float22bfloat162_rn(make_float2(v.z - f1.x, v.w - f1.y));
                    int c = shalf + j * 4;
                    *(uint32_t*)&sXh[srow * ST + c]     = *(uint32_t*)&h0;
                    *(uint32_t*)&sXh[srow * ST + c + 2] = *(uint32_t*)&h1;
                    *(uint32_t*)&sXl[srow * ST + c]     = *(uint32_t*)&l0;
                    *(uint32_t*)&sXl[srow * ST + c + 2] = *(uint32_t*)&l1;
                }
            } else {
#pragma unroll
                for (int j = 0; j < 8; j++) {
                    *(uint32_t*)&sXh[srow * ST + shalf + j * 2] = 0u;
                    *(uint32_t*)&sXl[srow * ST + shalf + j * 2] = 0u;
                }
            }
            // ---- stage W^T chunk (bf16, already split) ----
            const uint4* wh = (const uint4*)(Wh + srow * D + k0 + shalf);
            const uint4* wl = (const uint4*)(Wl + srow * D + k0 + shalf);
            uint4 a0 = wh[0], a1 = wh[1], b0 = wl[0], b1 = wl[1];
            uint4* dh = (uint4*)&sWh[srow * ST + shalf];
            uint4* dl = (uint4*)&sWl[srow * ST + shalf];
            dh[0] = a0; dh[1] = a1;
            dl[0] = b0; dl[1] = b1;
        }
        __syncthreads();

        // ---- MMAs over this k-chunk ----
#pragma unroll
        for (int ks = 0; ks < 2; ks++) {
            int kc = ks * 16 + 2 * t;
            uint32_t ah[2][4], al[2][4];
#pragma unroll
            for (int mt = 0; mt < 2; mt++) {
                int r = mr0 + mt * 16 + g;
                ah[mt][0] = *(const uint32_t*)&sXh[r * ST + kc];
                ah[mt][1] = *(const uint32_t*)&sXh[(r + 8) * ST + kc];
                ah[mt][2] = *(const uint32_t*)&sXh[r * ST + kc + 8];
                ah[mt][3] = *(const uint32_t*)&sXh[(r + 8) * ST + kc + 8];
                al[mt][0] = *(const uint32_t*)&sXl[r * ST + kc];
                al[mt][1] = *(const uint32_t*)&sXl[(r + 8) * ST + kc];
                al[mt][2] = *(const uint32_t*)&sXl[r * ST + kc + 8];
                al[mt][3] = *(const uint32_t*)&sXl[(r + 8) * ST + kc + 8];
            }
#pragma unroll
            for (int nt = 0; nt < 8; nt++) {
                int nr = nb + nt * 8 + g;
                uint32_t bh[2], bl[2];
                bh[0] = *(const uint32_t*)&sWh[nr * ST + kc];
                bh[1] = *(const uint32_t*)&sWh[nr * ST + kc + 8];
                bl[0] = *(const uint32_t*)&sWl[nr * ST + kc];
                bl[1] = *(const uint32_t*)&sWl[nr * ST + kc + 8];
#pragma unroll
                for (int mt = 0; mt < 2; mt++) {
                    MMA_BF16(acc[mt][nt], ah[mt], bh);   // hi*hi
                    MMA_BF16(acc[mt][nt], al[mt], bh);   // lo*hi
                    MMA_BF16(acc[mt][nt], ah[mt], bl);   // hi*lo
                }
            }
        }
    }

    // ---- epilogue: fragment -> g_h ----
#pragma unroll
    for (int mt = 0; mt < 2; mt++) {
        int r0 = row0 + mr0 + mt * 16 + g;
        int r1 = r0 + 8;
#pragma unroll
        for (int nt = 0; nt < 8; nt++) {
            int c = nb + nt * 8 + 2 * t;
            if (r0 < nrows)
                *(float2*)&g_h[(size_t)r0 * D + c] = make_float2(acc[mt][nt][0], acc[mt][nt][1]);
            if (r1 < nrows)
                *(float2*)&g_h[(size_t)r1 * D + c] = make_float2(acc[mt][nt][2], acc[mt][nt][3]);
        }
    }
}

// ===================== aggregation (+ optional fused head) ==================
template <bool FINAL>
__global__ void __launch_bounds__(256) k_agg(const float* __restrict__ b,
                                             const float* __restrict__ Wl,
                                             const float* __restrict__ bl,
                                             float* __restrict__ out, int n) {
    int warp = threadIdx.x >> 5, lane = threadIdx.x & 31;
    int i = blockIdx.x * 8 + warp;
    if (i >= n) return;
    float di = g_dinv[i];
    float ds = di * di;
    const float4* h4 = (const float4*)g_h;
    float4 hv = h4[i * 32 + lane];
    float4 bv = ((const float4*)b)[lane];
    float4 acc;
    acc.x = fmaf(hv.x, ds, bv.x);
    acc.y = fmaf(hv.y, ds, bv.y);
    acc.z = fmaf(hv.z, ds, bv.z);
    acc.w = fmaf(hv.w, ds, bv.w);
    int p0 = g_off[i], p1 = p0 + g_cnt[i];
    for (int p = p0; p < p1; p++) {
        int s = g_csrc[p];
        float nm = g_cnorm[p];
        float4 v = h4[s * 32 + lane];
        acc.x = fmaf(v.x, nm, acc.x);
        acc.y = fmaf(v.y, nm, acc.y);
        acc.z = fmaf(v.z, nm, acc.z);
        acc.w = fmaf(v.w, nm, acc.w);
    }
    if (!FINAL) {
        ((float4*)g_x)[i * 32 + lane] = acc;
    } else {
        float4 wv = ((const float4*)Wl)[lane];
        float a = fmaxf(acc.x, 0.f) * wv.x + fmaxf(acc.y, 0.f) * wv.y +
                  fmaxf(acc.z, 0.f) * wv.z + fmaxf(acc.w, 0.f) * wv.w;
#pragma unroll
        for (int o = 16; o; o >>= 1) a += __shfl_xor_sync(0xffffffffu, a, o);
        if (lane == 0) out[i] = a + bl[0];
    }
}

// ================================ launch ====================================
extern "C" void kernel_launch(void* const* d_in, const int* in_sizes, int n_in,
                              void* d_out, int out_size) {
    const float* wx = (const float*)d_in[0];
    const int*   ei = (const int*)d_in[1];     // int32 (JAX x64 disabled)
    const float* ew = (const float*)d_in[2];
    const float* W1 = (const float*)d_in[3];
    const float* b1 = (const float*)d_in[4];
    const float* W2 = (const float*)d_in[5];
    const float* b2 = (const float*)d_in[6];
    const float* Wl = (const float*)d_in[7];
    const float* bl = (const float*)d_in[8];
    float* out = (float*)d_out;

    int n = in_sizes[0] / D;   // 100000
    int e = in_sizes[2];       // 600000

    int nb = (n + 255) / 256;
    int eb = (e + 255) / 256;
    int gb = (n + TM - 1) / TM;

    k_wsplit<<<128, 256>>>(W1, W2);
    k_zero  <<<nb, 256>>>(n);
    k_count <<<eb, 256>>>(ei, ew, e);
    k_node  <<<nb, 256>>>(n);
    k_bucket<<<eb, 256>>>(ei, ew, e);

    // layer 1
    k_gemm_mma<false><<<gb, 256>>>(wx, 0, n);
    k_agg<false>     <<<(n + 7) / 8, 256>>>(b1, nullptr, nullptr, nullptr, n);
    // layer 2 (relu fused into staging) + head fused into aggregation
    k_gemm_mma<true> <<<gb, 256>>>(nullptr, 1, n);
    k_agg<true>      <<<(n + 7) / 8, 256>>>(b2, Wl, bl, out, n);
}

// round 9
// speedup vs baseline: 2.0592x; 1.0593x over previous
#include <cuda_runtime.h>
#include <cuda_bf16.h>
#include <cstdint>

#define NN 100000
#define EE 600000
#define D 128
#define TM 128           // rows per GEMM block
#define ST 40            // smem row stride in bf16 (32 data + 8 pad) -> conflict-free frags

// ---- static device scratch ----
__device__ float g_h[NN * D];
__device__ float g_x[NN * D];
__device__ float g_dinv[NN];
__device__ float g_degw[NN];
__device__ int   g_cnt[NN];
__device__ int   g_cur[NN];
__device__ int   g_off[NN];
__device__ int   g_total;
__device__ int   g_csrc[EE];
__device__ float g_cnorm[EE];
// pre-split W^T images, row-major [n][k] bf16: [matrix][hi/lo]
__device__ __align__(16) __nv_bfloat16 g_wimg[2][2][D * D];

// =========================== preprocessing ==================================
__global__ void k_zero(int n) {
    int i = blockIdx.x * blockDim.x + threadIdx.x;
    if (i < n) { g_degw[i] = 0.f; g_cnt[i] = 0; g_cur[i] = 0; }
    if (i == 0) g_total = 0;
}

// edge_index is int32 (JAX x64 disabled downgrades jnp.int64).
__global__ void k_count(const int* __restrict__ ei,
                        const float* __restrict__ ew, int e) {
    int i = blockIdx.x * blockDim.x + threadIdx.x;
    if (i < e) {
        int dst = ei[e + i];
        atomicAdd(&g_cnt[dst], 1);
        atomicAdd(&g_degw[dst], ew[i]);
    }
}

// per-node: dinv + CSR slot reservation (warp-scan + one atomic per warp)
__global__ void k_node(int n) {
    int i = blockIdx.x * blockDim.x + threadIdx.x;
    int lane = threadIdx.x & 31;
    if (i < n) g_dinv[i] = rsqrtf(g_degw[i] + 1.0f);
    int c = (i < n) ? g_cnt[i] : 0;
    int pfx = c;
#pragma unroll
    for (int o = 1; o < 32; o <<= 1) {
        int t = __shfl_up_sync(0xffffffffu, pfx, o);
        if (lane >= o) pfx += t;
    }
    int wsum = __shfl_sync(0xffffffffu, pfx, 31);
    int base = 0;
    if (lane == 31) base = atomicAdd(&g_total, wsum);
    base = __shfl_sync(0xffffffffu, base, 31);
    if (i < n) g_off[i] = base + pfx - c;
}

__global__ void k_bucket(const int* __restrict__ ei,
                         const float* __restrict__ ew, int e) {
    int i = blockIdx.x * blockDim.x + threadIdx.x;
    if (i < e) {
        int src = ei[i];
        int dst = ei[e + i];
        int pos = g_off[dst] + atomicAdd(&g_cur[dst], 1);
        g_csrc[pos] = src;
        g_cnorm[pos] = g_dinv[src] * ew[i] * g_dinv[dst];
    }
}

// split W1/W2 into bf16 hi/lo W^T images, row-major [n][k]
__global__ void k_wsplit(const float* __restrict__ W1,
                         const float* __restrict__ W2) {
    int i = blockIdx.x * blockDim.x + threadIdx.x;  // 0..32767
    int m = i >> 14;
    int idx = i & 16383;
    int k = idx >> 7, nn_ = idx & 127;
    const float* W = m ? W2 : W1;
    float w = W[k * D + nn_];
    __nv_bfloat16 h = __float2bfloat16(w);
    __nv_bfloat16 l = __float2bfloat16(w - __bfloat162float(h));
    g_wimg[m][0][nn_ * D + k] = h;   // W^T[n][k]
    g_wimg[m][1][nn_ * D + k] = l;
}

// ===================== tensor-core GEMM via mma.sync (bf16 3-MMA split) =====
#define MMA_BF16(d, a, b) \
    asm volatile("mma.sync.aligned.m16n8k16.row.col.f32.bf16.bf16.f32 " \
        "{%0,%1,%2,%3}, {%4,%5,%6,%7}, {%8,%9}, {%0,%1,%2,%3};" \
        : "+f"((d)[0]), "+f"((d)[1]), "+f"((d)[2]), "+f"((d)[3]) \
        : "r"((a)[0]), "r"((a)[1]), "r"((a)[2]), "r"((a)[3]), \
          "r"((b)[0]), "r"((b)[1]))

template <bool SRC_GX>
__global__ void __launch_bounds__(256) k_gemm_mma(const float* __restrict__ Xarg,
                                                  int bsel, int nrows) {
    __shared__ __nv_bfloat16 sXh[TM * ST];   // 10 KB each
    __shared__ __nv_bfloat16 sXl[TM * ST];
    __shared__ __nv_bfloat16 sWh[D * ST];
    __shared__ __nv_bfloat16 sWl[D * ST];

    int tid = threadIdx.x;
    int wid = tid >> 5, lane = tid & 31;
    int g = lane >> 2, t = lane & 3;      // frag group / thread-in-group
    int mr0 = (wid & 3) * 32;             // warp's 32 rows within the tile
    int nb  = (wid >> 2) * 64;            // warp's 64-col half

    int row0 = blockIdx.x * TM;
    const float* Xsrc = SRC_GX ? (const float*)g_x : Xarg;
    const __nv_bfloat16* Wh = g_wimg[bsel][0];
    const __nv_bfloat16* Wl = g_wimg[bsel][1];

    float acc[2][8][4];
#pragma unroll
    for (int a = 0; a < 2; a++)
#pragma unroll
        for (int b = 0; b < 8; b++)
#pragma unroll
            for (int c = 0; c < 4; c++) acc[a][b][c] = 0.f;

    int srow = tid >> 1;                  // staging: thread -> row, half
    int shalf = (tid & 1) * 16;

    for (int k0 = 0; k0 < D; k0 += 32) {
        __syncthreads();
        // ---- stage X chunk (fp32 -> bf16 hi/lo) ----
        {
            int grow = row0 + srow;
            if (grow < nrows) {
                const float4* xr = (const float4*)(Xsrc + (size_t)grow * D + k0 + shalf);
#pragma unroll
                for (int j = 0; j < 4; j++) {
                    float4 v = xr[j];
                    if (SRC_GX) {
                        v.x = fmaxf(v.x, 0.f); v.y = fmaxf(v.y, 0.f);
                        v.z = fmaxf(v.z, 0.f); v.w = fmaxf(v.w, 0.f);
                    }
                    __nv_bfloat162 h0 = __float22bfloat162_rn(make_float2(v.x, v.y));
                    __nv_bfloat162 h1 = __float22bfloat162_rn(make_float2(v.z, v.w));
                    float2 f0 = __bfloat1622float2(h0);
                    float2 f1 = __bfloat1622float2(h1);
                    __nv_bfloat162 l0 = __float22bfloat162_rn(make_float2(v.x - f0.x, v.y - f0.y));
                    __nv_bfloat162 l1 = __float22bfloat162_rn(make_float2(v.z - f1.x, v.w - f1.y));
                    int c = shalf + j * 4;
                    *(uint32_t*)&sXh[srow * ST + c]     = *(uint32_t*)&h0;
                    *(uint32_t*)&sXh[srow * ST + c + 2] = *(uint32_t*)&h1;
                    *(uint32_t*)&sXl[srow * ST + c]     = *(uint32_t*)&l0;
                    *(uint32_t*)&sXl[srow * ST + c + 2] = *(uint32_t*)&l1;
                }
            } else {
#pragma unroll
                for (int j = 0; j < 8; j++) {
                    *(uint32_t*)&sXh[srow * ST + shalf + j * 2] = 0u;
                    *(uint32_t*)&sXl[srow * ST + shalf + j * 2] = 0u;
                }
            }
            // ---- stage W^T chunk (bf16, already split) ----
            const uint4* wh = (const uint4*)(Wh + srow * D + k0 + shalf);
            const uint4* wl = (const uint4*)(Wl + srow * D + k0 + shalf);
            uint4 a0 = wh[0], a1 = wh[1], b0 = wl[0], b1 = wl[1];
            uint4* dh = (uint4*)&sWh[srow * ST + shalf];
            uint4* dl = (uint4*)&sWl[srow * ST + shalf];
            dh[0] = a0; dh[1] = a1;
            dl[0] = b0; dl[1] = b1;
        }
        __syncthreads();

        // ---- MMAs over this k-chunk ----
#pragma unroll
        for (int ks = 0; ks < 2; ks++) {
            int kc = ks * 16 + 2 * t;
            uint32_t ah[2][4], al[2][4];
#pragma unroll
            for (int mt = 0; mt < 2; mt++) {
                int r = mr0 + mt * 16 + g;
                ah[mt][0] = *(const uint32_t*)&sXh[r * ST + kc];
                ah[mt][1] = *(const uint32_t*)&sXh[(r + 8) * ST + kc];
                ah[mt][2] = *(const uint32_t*)&sXh[r * ST + kc + 8];
                ah[mt][3] = *(const uint32_t*)&sXh[(r + 8) * ST + kc + 8];
                al[mt][0] = *(const uint32_t*)&sXl[r * ST + kc];
                al[mt][1] = *(const uint32_t*)&sXl[(r + 8) * ST + kc];
                al[mt][2] = *(const uint32_t*)&sXl[r * ST + kc + 8];
                al[mt][3] = *(const uint32_t*)&sXl[(r + 8) * ST + kc + 8];
            }
#pragma unroll
            for (int nt = 0; nt < 8; nt++) {
                int nr = nb + nt * 8 + g;
                uint32_t bh[2], bl[2];
                bh[0] = *(const uint32_t*)&sWh[nr * ST + kc];
                bh[1] = *(const uint32_t*)&sWh[nr * ST + kc + 8];
                bl[0] = *(const uint32_t*)&sWl[nr * ST + kc];
                bl[1] = *(const uint32_t*)&sWl[nr * ST + kc + 8];
#pragma unroll
                for (int mt = 0; mt < 2; mt++) {
                    MMA_BF16(acc[mt][nt], ah[mt], bh);   // hi*hi
                    MMA_BF16(acc[mt][nt], al[mt], bh);   // lo*hi
                    MMA_BF16(acc[mt][nt], ah[mt], bl);   // hi*lo
                }
            }
        }
    }

    // ---- epilogue: fragment -> g_h ----
#pragma unroll
    for (int mt = 0; mt < 2; mt++) {
        int r0 = row0 + mr0 + mt * 16 + g;
        int r1 = r0 + 8;
#pragma unroll
        for (int nt = 0; nt < 8; nt++) {
            int c = nb + nt * 8 + 2 * t;
            if (r0 < nrows)
                *(float2*)&g_h[(size_t)r0 * D + c] = make_float2(acc[mt][nt][0], acc[mt][nt][1]);
            if (r1 < nrows)
                *(float2*)&g_h[(size_t)r1 * D + c] = make_float2(acc[mt][nt][2], acc[mt][nt][3]);
        }
    }
}

// ===================== aggregation (+ optional fused head) ==================
template <bool FINAL>
__global__ void __launch_bounds__(256) k_agg(const float* __restrict__ b,
                                             const float* __restrict__ Wl,
                                             const float* __restrict__ bl,
                                             float* __restrict__ out, int n) {
    int warp = threadIdx.x >> 5, lane = threadIdx.x & 31;
    int i = blockIdx.x * 8 + warp;
    if (i >= n) return;
    float di = g_dinv[i];
    float ds = di * di;
    const float4* h4 = (const float4*)g_h;
    float4 hv = h4[i * 32 + lane];
    float4 bv = ((const float4*)b)[lane];
    float4 acc;
    acc.x = fmaf(hv.x, ds, bv.x);
    acc.y = fmaf(hv.y, ds, bv.y);
    acc.z = fmaf(hv.z, ds, bv.z);
    acc.w = fmaf(hv.w, ds, bv.w);
    int p0 = g_off[i], p1 = p0 + g_cnt[i];
    for (int p = p0; p < p1; p++) {
        int s = g_csrc[p];
        float nm = g_cnorm[p];
        float4 v = h4[s * 32 + lane];
        acc.x = fmaf(v.x, nm, acc.x);
        acc.y = fmaf(v.y, nm, acc.y);
        acc.z = fmaf(v.z, nm, acc.z);
        acc.w = fmaf(v.w, nm, acc.w);
    }
    if (!FINAL) {
        ((float4*)g_x)[i * 32 + lane] = acc;
    } else {
        float4 wv = ((const float4*)Wl)[lane];
        float a = fmaxf(acc.x, 0.f) * wv.x + fmaxf(acc.y, 0.f) * wv.y +
                  fmaxf(acc.z, 0.f) * wv.z + fmaxf(acc.w, 0.f) * wv.w;
#pragma unroll
        for (int o = 16; o; o >>= 1) a += __shfl_xor_sync(0xffffffffu, a, o);
        if (lane == 0) out[i] = a + bl[0];
    }
}

// ================================ launch ====================================
extern "C" void kernel_launch(void* const* d_in, const int* in_sizes, int n_in,
                              void* d_out, int out_size) {
    const float* wx = (const float*)d_in[0];
    const int*   ei = (const int*)d_in[1];     // int32 (JAX x64 disabled)
    const float* ew = (const float*)d_in[2];
    const float* W1 = (const float*)d_in[3];
    const float* b1 = (const float*)d_in[4];
    const float* W2 = (const float*)d_in[5];
    const float* b2 = (const float*)d_in[6];
    const float* Wl = (const float*)d_in[7];
    const float* bl = (const float*)d_in[8];
    float* out = (float*)d_out;

    int n = in_sizes[0] / D;   // 100000
    int e = in_sizes[2];       // 600000

    int nb = (n + 255) / 256;
    int eb = (e + 255) / 256;
    int gb = (n + TM - 1) / TM;

    // Side stream + events for fork/join (host objects, created once on the
    // first -- uncaptured -- call; replays never re-run host code).
    static cudaStream_t s2 = nullptr;
    static cudaEvent_t evFork = nullptr, evJoin = nullptr;
    if (!s2) {
        cudaStreamCreateWithFlags(&s2, cudaStreamNonBlocking);
        cudaEventCreateWithFlags(&evFork, cudaEventDisableTiming);
        cudaEventCreateWithFlags(&evJoin, cudaEventDisableTiming);
    }

    // fork: edge/CSR chain on s2, weight-split + GEMM-1 on main stream
    cudaEventRecord(evFork, 0);
    cudaStreamWaitEvent(s2, evFork, 0);
    k_zero  <<<nb, 256, 0, s2>>>(n);
    k_count <<<eb, 256, 0, s2>>>(ei, ew, e);
    k_node  <<<nb, 256, 0, s2>>>(n);
    k_bucket<<<eb, 256, 0, s2>>>(ei, ew, e);
    cudaEventRecord(evJoin, s2);

    k_wsplit<<<128, 256>>>(W1, W2);
    k_gemm_mma<false><<<gb, 256>>>(wx, 0, n);

    // join: aggregation needs both g_h (main) and CSR (s2)
    cudaStreamWaitEvent(0, evJoin, 0);
    k_agg<false>     <<<(n + 7) / 8, 256>>>(b1, nullptr, nullptr, nullptr, n);
    // layer 2 (relu fused into staging) + head fused into aggregation
    k_gemm_mma<true> <<<gb, 256>>>(nullptr, 1, n);
    k_agg<true>      <<<(n + 7) / 8, 256>>>(b2, Wl, bl, out, n);
}